// round 1
// baseline (speedup 1.0000x reference)
#include <cuda_runtime.h>
#include <cstdint>

#define NB 32
#define NS 2048
#define DE 1024
#define NU 1024

#define TS 128
#define TU 64
#define TK 16

// Scratch (no allocations allowed) — referenced directly from device code.
__device__ float g_dp[NB * NU];          // dec_proj + b1
__device__ float g_e2[NB * NS];          // energies2 pre-softmax
__device__ float g_cpart[8 * NB * DE];   // context partials (split-S)

__device__ __forceinline__ unsigned long long dup2(float x) {
    unsigned long long r;
    asm("mov.b64 %0, {%1, %1};" : "=l"(r) : "f"(x));
    return r;
}
__device__ __forceinline__ void fma2(unsigned long long& d, unsigned long long a, unsigned long long b) {
    asm("fma.rn.f32x2 %0, %1, %2, %0;" : "+l"(d) : "l"(a), "l"(b));
}
__device__ __forceinline__ float lo32(unsigned long long v) {
    return __uint_as_float((unsigned)(v & 0xffffffffu));
}
__device__ __forceinline__ float hi32(unsigned long long v) {
    return __uint_as_float((unsigned)(v >> 32));
}

// ---------------- Kernel 1: dec_proj[b,u] = h_dec[b,:] @ W1[1024:2048,u] + b1[u] ----------------
__global__ void k_decproj(const float* __restrict__ hdec, const float* __restrict__ W1,
                          const float* __restrict__ b1) {
    int b = blockIdx.y;
    int u = blockIdx.x * 256 + threadIdx.x;
    const float* hd = hdec + b * DE;
    float acc = b1[u];
#pragma unroll 8
    for (int k = 0; k < DE; k++)
        acc = fmaf(hd[k], W1[(size_t)(DE + k) * NU + u], acc);
    g_dp[b * NU + u] = acc;
}

// ---------------- Kernel 2: fused e2[b,s] = relu(tanh(henc@W1enc + dp + b1) @ W2 + b2) ----------
__global__ __launch_bounds__(256) void k_energies(const float* __restrict__ henc,
                                                  const float* __restrict__ W1,
                                                  const float* __restrict__ W2,
                                                  const float* __restrict__ b2) {
    __shared__ float As[TK][TS + 2];  // pad=2: conflict-free transpose stores, 8B-aligned pair reads
    __shared__ float Bs[TK][TU];

    int tid = threadIdx.x;
    int tx = tid & 15;        // column group: cols u0 + tx*4 + j
    int ty = tid >> 4;        // row group: rows 2*ty + 32*ii + h
    int sblk = blockIdx.x, b = blockIdx.y;
    size_t base = ((size_t)b * NS + (size_t)sblk * TS) * DE;

    float e2part[8];
#pragma unroll
    for (int i = 0; i < 8; i++) e2part[i] = 0.f;

    for (int u0 = 0; u0 < NU; u0 += TU) {
        unsigned long long acc2[4][4];
#pragma unroll
        for (int ii = 0; ii < 4; ii++)
#pragma unroll
            for (int j = 0; j < 4; j++) acc2[ii][j] = 0ull;

        for (int k0 = 0; k0 < DE; k0 += TK) {
            // Load A tile 128x16 (transposed into As[k][row])
#pragma unroll
            for (int q = 0; q < 2; q++) {
                int idx = tid + q * 256;
                int row = idx >> 2;
                int kq = (idx & 3) << 2;
                float4 v = *(const float4*)(henc + base + (size_t)row * DE + k0 + kq);
                As[kq + 0][row] = v.x;
                As[kq + 1][row] = v.y;
                As[kq + 2][row] = v.z;
                As[kq + 3][row] = v.w;
            }
            // Load B tile 16x64
            {
                int k = tid >> 4;
                int uq = (tid & 15) << 2;
                float4 v = *(const float4*)(W1 + (size_t)(k0 + k) * NU + u0 + uq);
                *(float4*)&Bs[k][uq] = v;
            }
            __syncthreads();
#pragma unroll
            for (int k = 0; k < TK; k++) {
                float4 bv = *(const float4*)&Bs[k][tx << 2];
                unsigned long long bd[4];
                bd[0] = dup2(bv.x);
                bd[1] = dup2(bv.y);
                bd[2] = dup2(bv.z);
                bd[3] = dup2(bv.w);
                unsigned long long a2[4];
#pragma unroll
                for (int ii = 0; ii < 4; ii++)
                    a2[ii] = *(const unsigned long long*)&As[k][(ty << 1) + (ii << 5)];
#pragma unroll
                for (int ii = 0; ii < 4; ii++)
#pragma unroll
                    for (int j = 0; j < 4; j++)
                        fma2(acc2[ii][j], a2[ii], bd[j]);
            }
            __syncthreads();
        }
        // Epilogue: tanh + contract with W2 into per-row partials
#pragma unroll
        for (int j = 0; j < 4; j++) {
            int u = u0 + (tx << 2) + j;
            float dpu = g_dp[b * NU + u];
            float w2u = W2[u];
#pragma unroll
            for (int ii = 0; ii < 4; ii++) {
                float pl = lo32(acc2[ii][j]);
                float ph = hi32(acc2[ii][j]);
                e2part[ii * 2 + 0] = fmaf(tanhf(pl + dpu), w2u, e2part[ii * 2 + 0]);
                e2part[ii * 2 + 1] = fmaf(tanhf(ph + dpu), w2u, e2part[ii * 2 + 1]);
            }
        }
    }
    // Reduce across the 16 tx lanes (same ty -> same row set); fixed order, deterministic.
    float b2v = b2[0];
#pragma unroll
    for (int ii = 0; ii < 4; ii++) {
#pragma unroll
        for (int h = 0; h < 2; h++) {
            float v = e2part[ii * 2 + h];
            v += __shfl_xor_sync(0xffffffffu, v, 8);
            v += __shfl_xor_sync(0xffffffffu, v, 4);
            v += __shfl_xor_sync(0xffffffffu, v, 2);
            v += __shfl_xor_sync(0xffffffffu, v, 1);
            if (tx == 0) {
                int r = (ty << 1) + (ii << 5) + h;
                g_e2[b * NS + sblk * TS + r] = fmaxf(v + b2v, 0.f);
            }
        }
    }
}

// ---------------- Kernel 3: softmax over S per batch; writes attention weights ----------------
__global__ void k_softmax(float* __restrict__ attn) {
    int b = blockIdx.x, t = threadIdx.x;
    __shared__ float red[256];
    float v[8];
    float mx = -1e30f;
#pragma unroll
    for (int q = 0; q < 8; q++) {
        v[q] = g_e2[b * NS + t + 256 * q];
        mx = fmaxf(mx, v[q]);
    }
    red[t] = mx;
    __syncthreads();
    for (int o = 128; o > 0; o >>= 1) {
        if (t < o) red[t] = fmaxf(red[t], red[t + o]);
        __syncthreads();
    }
    mx = red[0];
    __syncthreads();
    float s = 0.f;
#pragma unroll
    for (int q = 0; q < 8; q++) {
        v[q] = expf(v[q] - mx);
        s += v[q];
    }
    red[t] = s;
    __syncthreads();
    for (int o = 128; o > 0; o >>= 1) {
        if (t < o) red[t] += red[t + o];
        __syncthreads();
    }
    float inv = 1.f / red[0];
#pragma unroll
    for (int q = 0; q < 8; q++) attn[b * NS + t + 256 * q] = v[q] * inv;
}

// ---------------- Kernel 4: context partials over S-chunks (no atomics: deterministic) --------
__global__ void k_ctxpart(const float* __restrict__ henc, const float* __restrict__ attn) {
    int sc = blockIdx.x, b = blockIdx.y, t = threadIdx.x;
    __shared__ float w[256];
    w[t] = attn[b * NS + sc * 256 + t];
    __syncthreads();
    int d = t * 4;
    float4 acc = make_float4(0.f, 0.f, 0.f, 0.f);
    const float* hp = henc + ((size_t)b * NS + (size_t)sc * 256) * DE + d;
#pragma unroll 4
    for (int s = 0; s < 256; s++) {
        float ww = w[s];
        float4 h = *(const float4*)(hp + (size_t)s * DE);
        acc.x = fmaf(ww, h.x, acc.x);
        acc.y = fmaf(ww, h.y, acc.y);
        acc.z = fmaf(ww, h.z, acc.z);
        acc.w = fmaf(ww, h.w, acc.w);
    }
    *(float4*)&g_cpart[(size_t)(sc * NB + b) * DE + d] = acc;
}

// ---------------- Kernel 5: reduce partials into context output ----------------
__global__ void k_ctxred(float* __restrict__ ctx) {
    int i = blockIdx.x * 256 + threadIdx.x;  // 0..32767
    int b = i >> 10, d = i & 1023;
    float s = 0.f;
#pragma unroll
    for (int sc = 0; sc < 8; sc++) s += g_cpart[(size_t)(sc * NB + b) * DE + d];
    ctx[i] = s;
}

extern "C" void kernel_launch(void* const* d_in, const int* in_sizes, int n_in,
                              void* d_out, int out_size) {
    const float* henc = (const float*)d_in[0];
    const float* hdec = (const float*)d_in[1];
    const float* W1 = (const float*)d_in[2];
    const float* b1 = (const float*)d_in[3];
    const float* W2 = (const float*)d_in[4];
    const float* b2 = (const float*)d_in[5];
    float* out = (float*)d_out;
    float* ctx = out;                 // [32,1024]
    float* attn = out + NB * DE;      // [32,2048,1]

    k_decproj<<<dim3(4, NB), 256>>>(hdec, W1, b1);
    k_energies<<<dim3(NS / TS, NB), 256>>>(henc, W1, W2, b2);
    k_softmax<<<NB, 256>>>(attn);
    k_ctxpart<<<dim3(8, NB), 256>>>(henc, attn);
    k_ctxred<<<128, 256>>>(ctx);
}

// round 3
// speedup vs baseline: 3.5745x; 3.5745x over previous
#include <cuda_runtime.h>
#include <cuda_bf16.h>
#include <cstdint>

#define NB 32
#define NS 2048
#define DE 1024
#define NU 1024

// ---------------- scratch (static device arrays; no runtime allocation) ----------------
__device__ float g_dp[NB * NU];                 // dec_proj + b1
__device__ float g_e2[NB * NS];                 // energies2 pre-softmax
__device__ float g_cpart[16 * NB * DE];         // context partials
__device__ __nv_bfloat16 g_w1t_hi[NU * DE];     // W1enc^T hi  [u][k]
__device__ __nv_bfloat16 g_w1t_lo[NU * DE];     // W1enc^T lo  [u][k]
__device__ __nv_bfloat16 g_ahi[(size_t)NB * NS * DE];  // henc hi  [row][k]
__device__ __nv_bfloat16 g_alo[(size_t)NB * NS * DE];  // henc lo  [row][k]

// ---------------- helpers ----------------
__device__ __forceinline__ uint32_t smem_u32(const void* p) {
    uint32_t a;
    asm("{ .reg .u64 t; cvta.to.shared.u64 t, %1; cvt.u32.u64 %0, t; }" : "=r"(a) : "l"(p));
    return a;
}
#define SWZ(x) ((x) ^ (((x) >> 3) & 0x70))

__device__ __forceinline__ void cpa16(uint32_t dst, const void* src) {
    asm volatile("cp.async.cg.shared.global [%0], [%1], 16;" :: "r"(dst), "l"(src));
}
__device__ __forceinline__ void ldsm4(uint32_t* r, uint32_t addr) {
    asm volatile("ldmatrix.sync.aligned.m8n8.x4.shared.b16 {%0,%1,%2,%3}, [%4];"
                 : "=r"(r[0]), "=r"(r[1]), "=r"(r[2]), "=r"(r[3]) : "r"(addr));
}
__device__ __forceinline__ void mma16816(float* c, const uint32_t* a, uint32_t b0, uint32_t b1) {
    asm volatile(
        "mma.sync.aligned.m16n8k16.row.col.f32.bf16.bf16.f32 "
        "{%0,%1,%2,%3}, {%4,%5,%6,%7}, {%8,%9}, {%0,%1,%2,%3};"
        : "+f"(c[0]), "+f"(c[1]), "+f"(c[2]), "+f"(c[3])
        : "r"(a[0]), "r"(a[1]), "r"(a[2]), "r"(a[3]), "r"(b0), "r"(b1));
}
__device__ __forceinline__ float tanh_fast(float x) {
    float t;
    asm("tanh.approx.f32 %0, %1;" : "=f"(t) : "f"(x));
    return t;
}

// ---------------- Kernel A: split henc fp32 -> bf16 hi/lo ----------------
__global__ void k_asplit(const float* __restrict__ henc) {
    size_t i = (size_t)blockIdx.x * 256 + threadIdx.x;  // one float4 per thread
    float4 v = ((const float4*)henc)[i];
    __nv_bfloat162 h0 = __floats2bfloat162_rn(v.x, v.y);
    __nv_bfloat162 h1 = __floats2bfloat162_rn(v.z, v.w);
    float2 f0 = __bfloat1622float2(h0);
    float2 f1 = __bfloat1622float2(h1);
    __nv_bfloat162 l0 = __floats2bfloat162_rn(v.x - f0.x, v.y - f0.y);
    __nv_bfloat162 l1 = __floats2bfloat162_rn(v.z - f1.x, v.w - f1.y);
    ((uint2*)g_ahi)[i] = make_uint2(*(uint32_t*)&h0, *(uint32_t*)&h1);
    ((uint2*)g_alo)[i] = make_uint2(*(uint32_t*)&l0, *(uint32_t*)&l1);
}

// ---------------- Kernel 0: split+transpose W1enc into bf16 hi/lo [u][k] ----------------
__global__ void k_w1split(const float* __restrict__ W1) {
    __shared__ float t[32][33];
    int k0 = blockIdx.x * 32, u0 = blockIdx.y * 32;
    int tx = threadIdx.x, ty = threadIdx.y;  // 32x8
#pragma unroll
    for (int i = 0; i < 32; i += 8)
        t[ty + i][tx] = W1[(size_t)(k0 + ty + i) * NU + u0 + tx];
    __syncthreads();
#pragma unroll
    for (int i = 0; i < 32; i += 8) {
        float v = t[tx][ty + i];
        size_t o = (size_t)(u0 + ty + i) * DE + k0 + tx;
        __nv_bfloat16 h = __float2bfloat16(v);
        g_w1t_hi[o] = h;
        g_w1t_lo[o] = __float2bfloat16(v - __bfloat162float(h));
    }
}

// ---------------- Kernel 1: dec_proj ----------------
__global__ void k_decproj(const float* __restrict__ hdec, const float* __restrict__ W1,
                          const float* __restrict__ b1) {
    int b = blockIdx.y;
    int u = blockIdx.x * 256 + threadIdx.x;
    const float* hd = hdec + b * DE;
    float acc = b1[u];
#pragma unroll 8
    for (int k = 0; k < DE; k++)
        acc = fmaf(hd[k], W1[(size_t)(DE + k) * NU + u], acc);
    g_dp[b * NU + u] = acc;
}

// ---------------- Kernel 2: mma.sync bf16x3 fused energies ----------------
// smem: 3 stage buffers (A 16KB + B 32KB each), then dp, w2, e2buf
#define STG_BYTES 49152
#define SM_DP (3 * STG_BYTES)          // 147456, 4KB
#define SM_W2 (SM_DP + 4096)           // 4KB
#define SM_EBUF (SM_W2 + 4096)         // 4*128 floats = 2KB
#define SM_TOTAL (SM_EBUF + 2048)      // 157696

__global__ __launch_bounds__(256, 1) void k_energies_mma(const float* __restrict__ W2,
                                                         const float* __restrict__ b2) {
    extern __shared__ char smem[];
    uint32_t sbase = smem_u32(smem);
    int tid = threadIdx.x, lane = tid & 31, wid = tid >> 5;
    int mwarp = wid >> 2, nwarp = wid & 3;
    int sblk = blockIdx.x, b = blockIdx.y;
    size_t rowbase = (size_t)b * NS + (size_t)sblk * 128;

    float* dp_s = (float*)(smem + SM_DP);
    float* w2_s = (float*)(smem + SM_W2);
    float* e2buf = (float*)(smem + SM_EBUF);
    for (int i = tid; i < NU; i += 256) {
        dp_s[i] = g_dp[b * NU + i];
        w2_s[i] = W2[i];
    }
    for (int i = tid; i < 512; i += 256) e2buf[i] = 0.f;
    __syncthreads();

    // per-thread ldmatrix base offsets (within a stage buffer), kk=0
    uint32_t a_off[4], b_off[4];
#pragma unroll
    for (int mf = 0; mf < 4; mf++) {
        int r = mwarp * 64 + mf * 16 + (lane & 15);
        int kb = (lane >> 4) * 16;  // bytes
        a_off[mf] = SWZ((uint32_t)(r * 128 + kb));
    }
#pragma unroll
    for (int nf2 = 0; nf2 < 4; nf2++) {
        int n = nwarp * 64 + nf2 * 16 + ((lane >> 4) & 1) * 8 + (lane & 7);
        int kb = ((lane >> 3) & 1) * 16;  // bytes
        b_off[nf2] = SWZ((uint32_t)(n * 128 + kb));
    }

    for (int uc = 0; uc < 4; uc++) {
        int u0 = uc * 256;
        float acc[4][8][4];
#pragma unroll
        for (int mf = 0; mf < 4; mf++)
#pragma unroll
            for (int nf = 0; nf < 8; nf++)
#pragma unroll
                for (int j = 0; j < 4; j++) acc[mf][nf][j] = 0.f;

        auto issue = [&](int st) {
            int seg = st >> 4;
            int k0 = (st & 15) << 6;
            uint32_t sA = sbase + (uint32_t)(st % 3) * STG_BYTES;
            uint32_t sB = sA + 16384;
            const __nv_bfloat16* ga = (seg == 2) ? g_alo : g_ahi;
            const __nv_bfloat16* gb = (seg == 1) ? g_w1t_lo : g_w1t_hi;
#pragma unroll
            for (int i = 0; i < 4; i++) {
                int idx = i * 256 + tid;
                int r = idx >> 3, kc = idx & 7;
                cpa16(sA + SWZ((uint32_t)(r * 128 + kc * 16)),
                      ga + (rowbase + r) * DE + k0 + kc * 8);
            }
#pragma unroll
            for (int i = 0; i < 8; i++) {
                int idx = i * 256 + tid;
                int r = idx >> 3, kc = idx & 7;
                cpa16(sB + SWZ((uint32_t)(r * 128 + kc * 16)),
                      gb + (size_t)(u0 + r) * DE + k0 + kc * 8);
            }
            asm volatile("cp.async.commit_group;" ::: "memory");
        };

        issue(0);
        issue(1);
        for (int st = 0; st < 48; st++) {
            if (st + 2 < 48) {
                issue(st + 2);
                asm volatile("cp.async.wait_group 2;" ::: "memory");
            } else if (st + 1 < 48) {
                asm volatile("cp.async.wait_group 1;" ::: "memory");
            } else {
                asm volatile("cp.async.wait_group 0;" ::: "memory");
            }
            __syncthreads();
            uint32_t abase = sbase + (uint32_t)(st % 3) * STG_BYTES;
            uint32_t bbase = abase + 16384;
#pragma unroll
            for (int kk = 0; kk < 4; kk++) {
                uint32_t a[4][4], bq[4][4];
#pragma unroll
                for (int mf = 0; mf < 4; mf++) ldsm4(a[mf], abase + (a_off[mf] ^ (kk << 5)));
#pragma unroll
                for (int nf2 = 0; nf2 < 4; nf2++) ldsm4(bq[nf2], bbase + (b_off[nf2] ^ (kk << 5)));
#pragma unroll
                for (int mf = 0; mf < 4; mf++)
#pragma unroll
                    for (int nf = 0; nf < 8; nf++) {
                        int nf2 = nf >> 1, h = (nf & 1) * 2;
                        mma16816(acc[mf][nf], a[mf], bq[nf2][h], bq[nf2][h + 1]);
                    }
            }
            __syncthreads();
        }

        // epilogue: tanh + W2 contraction
        float rowsum[4][2];
#pragma unroll
        for (int mf = 0; mf < 4; mf++) {
            rowsum[mf][0] = 0.f;
            rowsum[mf][1] = 0.f;
        }
#pragma unroll
        for (int mf = 0; mf < 4; mf++)
#pragma unroll
            for (int nf = 0; nf < 8; nf++)
#pragma unroll
                for (int j = 0; j < 4; j++) {
                    int u = u0 + nwarp * 64 + nf * 8 + (lane & 3) * 2 + (j & 1);
                    float e1 = acc[mf][nf][j] + dp_s[u];
                    rowsum[mf][j >> 1] = fmaf(tanh_fast(e1), w2_s[u], rowsum[mf][j >> 1]);
                }
#pragma unroll
        for (int mf = 0; mf < 4; mf++)
#pragma unroll
            for (int hh = 0; hh < 2; hh++) {
                float v = rowsum[mf][hh];
                v += __shfl_xor_sync(0xffffffffu, v, 1);
                v += __shfl_xor_sync(0xffffffffu, v, 2);
                if ((lane & 3) == 0) {
                    int row = mwarp * 64 + mf * 16 + (lane >> 2) + hh * 8;
                    e2buf[nwarp * 128 + row] += v;
                }
            }
        __syncthreads();
    }

    if (tid < 128) {
        float v = e2buf[tid] + e2buf[128 + tid] + e2buf[256 + tid] + e2buf[384 + tid] + b2[0];
        g_e2[b * NS + sblk * 128 + tid] = fmaxf(v, 0.f);
    }
}

// ---------------- Kernel 3: softmax ----------------
__global__ void k_softmax(float* __restrict__ attn) {
    int b = blockIdx.x, t = threadIdx.x;
    __shared__ float red[256];
    float v[8];
    float mx = -1e30f;
#pragma unroll
    for (int q = 0; q < 8; q++) {
        v[q] = g_e2[b * NS + t + 256 * q];
        mx = fmaxf(mx, v[q]);
    }
    red[t] = mx;
    __syncthreads();
    for (int o = 128; o > 0; o >>= 1) {
        if (t < o) red[t] = fmaxf(red[t], red[t + o]);
        __syncthreads();
    }
    mx = red[0];
    __syncthreads();
    float s = 0.f;
#pragma unroll
    for (int q = 0; q < 8; q++) {
        v[q] = expf(v[q] - mx);
        s += v[q];
    }
    red[t] = s;
    __syncthreads();
    for (int o = 128; o > 0; o >>= 1) {
        if (t < o) red[t] += red[t + o];
        __syncthreads();
    }
    float inv = 1.f / red[0];
#pragma unroll
    for (int q = 0; q < 8; q++) attn[b * NS + t + 256 * q] = v[q] * inv;
}

// ---------------- Kernel 4: context partials ----------------
__global__ void k_ctxpart(const float* __restrict__ henc, const float* __restrict__ attn) {
    int sc = blockIdx.x, b = blockIdx.y, t = threadIdx.x;
    __shared__ float w[128];
    if (t < 128) w[t] = attn[b * NS + sc * 128 + t];
    __syncthreads();
    int d = t * 4;
    float4 acc = make_float4(0.f, 0.f, 0.f, 0.f);
    const float* hp = henc + ((size_t)b * NS + (size_t)sc * 128) * DE + d;
#pragma unroll 4
    for (int s = 0; s < 128; s++) {
        float ww = w[s];
        float4 h = *(const float4*)(hp + (size_t)s * DE);
        acc.x = fmaf(ww, h.x, acc.x);
        acc.y = fmaf(ww, h.y, acc.y);
        acc.z = fmaf(ww, h.z, acc.z);
        acc.w = fmaf(ww, h.w, acc.w);
    }
    *(float4*)&g_cpart[(size_t)(sc * NB + b) * DE + d] = acc;
}

// ---------------- Kernel 5: reduce ----------------
__global__ void k_ctxred(float* __restrict__ ctx) {
    int i = blockIdx.x * 256 + threadIdx.x;
    int b = i >> 10, d = i & 1023;
    float s = 0.f;
#pragma unroll
    for (int sc = 0; sc < 16; sc++) s += g_cpart[(size_t)(sc * NB + b) * DE + d];
    ctx[i] = s;
}

extern "C" void kernel_launch(void* const* d_in, const int* in_sizes, int n_in,
                              void* d_out, int out_size) {
    const float* henc = (const float*)d_in[0];
    const float* hdec = (const float*)d_in[1];
    const float* W1 = (const float*)d_in[2];
    const float* b1 = (const float*)d_in[3];
    const float* W2 = (const float*)d_in[4];
    const float* b2 = (const float*)d_in[5];
    float* out = (float*)d_out;
    float* ctx = out;             // [32,1024]
    float* attn = out + NB * DE;  // [32,2048,1]

    cudaFuncSetAttribute(k_energies_mma, cudaFuncAttributeMaxDynamicSharedMemorySize, SM_TOTAL);

    k_asplit<<<(NB * NS * DE) / (256 * 4), 256>>>(henc);
    k_w1split<<<dim3(32, 32), dim3(32, 8)>>>(W1);
    k_decproj<<<dim3(4, NB), 256>>>(hdec, W1, b1);
    k_energies_mma<<<dim3(16, NB), 256, SM_TOTAL>>>(W2, b2);
    k_softmax<<<NB, 256>>>(attn);
    k_ctxpart<<<dim3(16, NB), 256>>>(henc, attn);
    k_ctxred<<<128, 256>>>(ctx);
}

// round 4
// speedup vs baseline: 3.6201x; 1.0128x over previous
#include <cuda_runtime.h>
#include <cuda_bf16.h>
#include <cstdint>

#define NB 32
#define NS 2048
#define DE 1024
#define NU 1024

// ---------------- scratch (static device arrays; no runtime allocation) ----------------
__device__ float g_dp[NB * NU];                 // dec_proj + b1
__device__ float g_e2[NB * NS];                 // energies2 pre-softmax
__device__ float g_cpart[16 * NB * DE];         // context partials
__device__ __nv_bfloat16 g_w1t_hi[NU * DE];     // W1enc^T hi  [u][k]
__device__ __nv_bfloat16 g_w1t_lo[NU * DE];     // W1enc^T lo  [u][k]
__device__ __nv_bfloat16 g_ahi[(size_t)NB * NS * DE];  // henc hi  [row][k]
__device__ __nv_bfloat16 g_alo[(size_t)NB * NS * DE];  // henc lo  [row][k]

// ---------------- helpers ----------------
__device__ __forceinline__ uint32_t smem_u32(const void* p) {
    uint32_t a;
    asm("{ .reg .u64 t; cvta.to.shared.u64 t, %1; cvt.u32.u64 %0, t; }" : "=r"(a) : "l"(p));
    return a;
}
#define SWZ(x) ((x) ^ (((x) >> 3) & 0x70))

__device__ __forceinline__ void cpa16(uint32_t dst, const void* src) {
    asm volatile("cp.async.cg.shared.global [%0], [%1], 16;" :: "r"(dst), "l"(src));
}
__device__ __forceinline__ void ldsm4(uint32_t* r, uint32_t addr) {
    asm volatile("ldmatrix.sync.aligned.m8n8.x4.shared.b16 {%0,%1,%2,%3}, [%4];"
                 : "=r"(r[0]), "=r"(r[1]), "=r"(r[2]), "=r"(r[3]) : "r"(addr));
}
__device__ __forceinline__ void mma16816(float* c, const uint32_t* a, uint32_t b0, uint32_t b1) {
    asm volatile(
        "mma.sync.aligned.m16n8k16.row.col.f32.bf16.bf16.f32 "
        "{%0,%1,%2,%3}, {%4,%5,%6,%7}, {%8,%9}, {%0,%1,%2,%3};"
        : "+f"(c[0]), "+f"(c[1]), "+f"(c[2]), "+f"(c[3])
        : "r"(a[0]), "r"(a[1]), "r"(a[2]), "r"(a[3]), "r"(b0), "r"(b1));
}
__device__ __forceinline__ float tanh_fast(float x) {
    float t;
    asm("tanh.approx.f32 %0, %1;" : "=f"(t) : "f"(x));
    return t;
}

// ---------------- Kernel A: split henc fp32 -> bf16 hi/lo ----------------
__global__ void k_asplit(const float* __restrict__ henc) {
    size_t i = (size_t)blockIdx.x * 256 + threadIdx.x;  // one float4 per thread
    float4 v = ((const float4*)henc)[i];
    __nv_bfloat162 h0 = __floats2bfloat162_rn(v.x, v.y);
    __nv_bfloat162 h1 = __floats2bfloat162_rn(v.z, v.w);
    float2 f0 = __bfloat1622float2(h0);
    float2 f1 = __bfloat1622float2(h1);
    __nv_bfloat162 l0 = __floats2bfloat162_rn(v.x - f0.x, v.y - f0.y);
    __nv_bfloat162 l1 = __floats2bfloat162_rn(v.z - f1.x, v.w - f1.y);
    ((uint2*)g_ahi)[i] = make_uint2(*(uint32_t*)&h0, *(uint32_t*)&h1);
    ((uint2*)g_alo)[i] = make_uint2(*(uint32_t*)&l0, *(uint32_t*)&l1);
}

// ---------------- Kernel 0: split+transpose W1enc into bf16 hi/lo [u][k] ----------------
__global__ void k_w1split(const float* __restrict__ W1) {
    __shared__ float t[32][33];
    int k0 = blockIdx.x * 32, u0 = blockIdx.y * 32;
    int tx = threadIdx.x, ty = threadIdx.y;  // 32x8
#pragma unroll
    for (int i = 0; i < 32; i += 8)
        t[ty + i][tx] = W1[(size_t)(k0 + ty + i) * NU + u0 + tx];
    __syncthreads();
#pragma unroll
    for (int i = 0; i < 32; i += 8) {
        float v = t[tx][ty + i];
        size_t o = (size_t)(u0 + ty + i) * DE + k0 + tx;
        __nv_bfloat16 h = __float2bfloat16(v);
        g_w1t_hi[o] = h;
        g_w1t_lo[o] = __float2bfloat16(v - __bfloat162float(h));
    }
}

// ---------------- Kernel 1: dec_proj ----------------
__global__ void k_decproj(const float* __restrict__ hdec, const float* __restrict__ W1,
                          const float* __restrict__ b1) {
    int b = blockIdx.y;
    int u = blockIdx.x * 256 + threadIdx.x;
    const float* hd = hdec + b * DE;
    float acc = b1[u];
#pragma unroll 8
    for (int k = 0; k < DE; k++)
        acc = fmaf(hd[k], W1[(size_t)(DE + k) * NU + u], acc);
    g_dp[b * NU + u] = acc;
}

// ---------------- Kernel 2: mma.sync bf16x3 fused energies (2 CTA/SM) ----------------
// CTA tile 128 rows x 128 u. 8 warps of 64x32. K-stage 64, 2-stage cp.async pipeline.
#define STG_BYTES 32768
#define SM_DP (2 * STG_BYTES)          // 65536, 4KB
#define SM_W2 (SM_DP + 4096)
#define SM_EBUF (SM_W2 + 4096)         // 512 floats
#define SM_TOTAL (SM_EBUF + 2048)      // 75776

__global__ __launch_bounds__(256, 2) void k_energies_mma(const float* __restrict__ W2,
                                                         const float* __restrict__ b2) {
    extern __shared__ char smem[];
    uint32_t sbase = smem_u32(smem);
    int tid = threadIdx.x, lane = tid & 31, wid = tid >> 5;
    int mwarp = wid >> 2, nwarp = wid & 3;  // 2 x 4
    int sblk = blockIdx.x, b = blockIdx.y;
    size_t rowbase = (size_t)b * NS + (size_t)sblk * 128;

    float* dp_s = (float*)(smem + SM_DP);
    float* w2_s = (float*)(smem + SM_W2);
    float* e2buf = (float*)(smem + SM_EBUF);
    for (int i = tid; i < NU; i += 256) {
        dp_s[i] = g_dp[b * NU + i];
        w2_s[i] = W2[i];
    }
    for (int i = tid; i < 512; i += 256) e2buf[i] = 0.f;
    __syncthreads();

    // ldmatrix per-thread base offsets (within a stage buffer)
    uint32_t a_off[4], b_off[2];
#pragma unroll
    for (int mf = 0; mf < 4; mf++) {
        int r = mwarp * 64 + mf * 16 + (lane & 15);
        int kb = (lane >> 4) * 16;
        a_off[mf] = SWZ((uint32_t)(r * 128 + kb));
    }
#pragma unroll
    for (int nf2 = 0; nf2 < 2; nf2++) {
        int n = nwarp * 32 + nf2 * 16 + ((lane >> 4) & 1) * 8 + (lane & 7);
        int kb = ((lane >> 3) & 1) * 16;
        b_off[nf2] = SWZ((uint32_t)(n * 128 + kb));
    }

    // issue one stage: fst in [0,384). uc = fst/48, within-uc: seg=(fst%48)>>4, k0=(fst%48&15)*64
    auto issue = [&](int fst) {
        int uc = fst / 48;
        int st = fst - uc * 48;
        int seg = st >> 4;
        int k0 = (st & 15) << 6;
        int u0 = uc << 7;
        uint32_t sA = sbase + (uint32_t)(fst & 1) * STG_BYTES;
        uint32_t sB = sA + 16384;
        const __nv_bfloat16* ga = (seg == 2) ? g_alo : g_ahi;
        const __nv_bfloat16* gb = (seg == 1) ? g_w1t_lo : g_w1t_hi;
#pragma unroll
        for (int i = 0; i < 4; i++) {
            int idx = i * 256 + tid;
            int r = idx >> 3, kc = idx & 7;
            cpa16(sA + SWZ((uint32_t)(r * 128 + kc * 16)),
                  ga + (rowbase + r) * DE + k0 + kc * 8);
        }
#pragma unroll
        for (int i = 0; i < 4; i++) {
            int idx = i * 256 + tid;
            int r = idx >> 3, kc = idx & 7;
            cpa16(sB + SWZ((uint32_t)(r * 128 + kc * 16)),
                  gb + (size_t)(u0 + r) * DE + k0 + kc * 8);
        }
        asm volatile("cp.async.commit_group;" ::: "memory");
    };

    float acc[4][4][4];
#pragma unroll
    for (int mf = 0; mf < 4; mf++)
#pragma unroll
        for (int nf = 0; nf < 4; nf++)
#pragma unroll
            for (int j = 0; j < 4; j++) acc[mf][nf][j] = 0.f;

    issue(0);
    for (int fst = 0; fst < 384; fst++) {
        if (fst + 1 < 384) {
            issue(fst + 1);
            asm volatile("cp.async.wait_group 1;" ::: "memory");
        } else {
            asm volatile("cp.async.wait_group 0;" ::: "memory");
        }
        __syncthreads();
        uint32_t abase = sbase + (uint32_t)(fst & 1) * STG_BYTES;
        uint32_t bbase = abase + 16384;
#pragma unroll
        for (int kk = 0; kk < 4; kk++) {
            uint32_t a[4][4], bq[2][4];
#pragma unroll
            for (int mf = 0; mf < 4; mf++) ldsm4(a[mf], abase + (a_off[mf] ^ (kk << 5)));
#pragma unroll
            for (int nf2 = 0; nf2 < 2; nf2++) ldsm4(bq[nf2], bbase + (b_off[nf2] ^ (kk << 5)));
#pragma unroll
            for (int mf = 0; mf < 4; mf++)
#pragma unroll
                for (int nf = 0; nf < 4; nf++) {
                    int nf2 = nf >> 1, h = (nf & 1) * 2;
                    mma16816(acc[mf][nf], a[mf], bq[nf2][h], bq[nf2][h + 1]);
                }
        }
        __syncthreads();

        // end of a u-chunk (48 stages): fused tanh + W2 epilogue (overlaps next uc's loads
        // and the co-resident CTA's MMA stream)
        if (fst % 48 == 47) {
            int u0 = (fst / 48) << 7;
            float rowsum[4][2];
#pragma unroll
            for (int mf = 0; mf < 4; mf++) {
                rowsum[mf][0] = 0.f;
                rowsum[mf][1] = 0.f;
            }
#pragma unroll
            for (int mf = 0; mf < 4; mf++)
#pragma unroll
                for (int nf = 0; nf < 4; nf++)
#pragma unroll
                    for (int j = 0; j < 4; j++) {
                        int u = u0 + nwarp * 32 + nf * 8 + (lane & 3) * 2 + (j & 1);
                        float e1 = acc[mf][nf][j] + dp_s[u];
                        rowsum[mf][j >> 1] = fmaf(tanh_fast(e1), w2_s[u], rowsum[mf][j >> 1]);
                        acc[mf][nf][j] = 0.f;
                    }
#pragma unroll
            for (int mf = 0; mf < 4; mf++)
#pragma unroll
                for (int hh = 0; hh < 2; hh++) {
                    float v = rowsum[mf][hh];
                    v += __shfl_xor_sync(0xffffffffu, v, 1);
                    v += __shfl_xor_sync(0xffffffffu, v, 2);
                    if ((lane & 3) == 0) {
                        int row = mwarp * 64 + mf * 16 + (lane >> 2) + hh * 8;
                        e2buf[nwarp * 128 + row] += v;
                    }
                }
        }
    }
    __syncthreads();
    if (tid < 128) {
        float v = e2buf[tid] + e2buf[128 + tid] + e2buf[256 + tid] + e2buf[384 + tid] + b2[0];
        g_e2[b * NS + sblk * 128 + tid] = fmaxf(v, 0.f);
    }
}

// ---------------- Kernel 3: softmax ----------------
__global__ void k_softmax(float* __restrict__ attn) {
    int b = blockIdx.x, t = threadIdx.x;
    __shared__ float red[256];
    float v[8];
    float mx = -1e30f;
#pragma unroll
    for (int q = 0; q < 8; q++) {
        v[q] = g_e2[b * NS + t + 256 * q];
        mx = fmaxf(mx, v[q]);
    }
    red[t] = mx;
    __syncthreads();
    for (int o = 128; o > 0; o >>= 1) {
        if (t < o) red[t] = fmaxf(red[t], red[t + o]);
        __syncthreads();
    }
    mx = red[0];
    __syncthreads();
    float s = 0.f;
#pragma unroll
    for (int q = 0; q < 8; q++) {
        v[q] = expf(v[q] - mx);
        s += v[q];
    }
    red[t] = s;
    __syncthreads();
    for (int o = 128; o > 0; o >>= 1) {
        if (t < o) red[t] += red[t + o];
        __syncthreads();
    }
    float inv = 1.f / red[0];
#pragma unroll
    for (int q = 0; q < 8; q++) attn[b * NS + t + 256 * q] = v[q] * inv;
}

// ---------------- Kernel 4: context partials ----------------
__global__ void k_ctxpart(const float* __restrict__ henc, const float* __restrict__ attn) {
    int sc = blockIdx.x, b = blockIdx.y, t = threadIdx.x;
    __shared__ float w[128];
    if (t < 128) w[t] = attn[b * NS + sc * 128 + t];
    __syncthreads();
    int d = t * 4;
    float4 acc = make_float4(0.f, 0.f, 0.f, 0.f);
    const float* hp = henc + ((size_t)b * NS + (size_t)sc * 128) * DE + d;
#pragma unroll 4
    for (int s = 0; s < 128; s++) {
        float ww = w[s];
        float4 h = *(const float4*)(hp + (size_t)s * DE);
        acc.x = fmaf(ww, h.x, acc.x);
        acc.y = fmaf(ww, h.y, acc.y);
        acc.z = fmaf(ww, h.z, acc.z);
        acc.w = fmaf(ww, h.w, acc.w);
    }
    *(float4*)&g_cpart[(size_t)(sc * NB + b) * DE + d] = acc;
}

// ---------------- Kernel 5: reduce ----------------
__global__ void k_ctxred(float* __restrict__ ctx) {
    int i = blockIdx.x * 256 + threadIdx.x;
    int b = i >> 10, d = i & 1023;
    float s = 0.f;
#pragma unroll
    for (int sc = 0; sc < 16; sc++) s += g_cpart[(size_t)(sc * NB + b) * DE + d];
    ctx[i] = s;
}

extern "C" void kernel_launch(void* const* d_in, const int* in_sizes, int n_in,
                              void* d_out, int out_size) {
    const float* henc = (const float*)d_in[0];
    const float* hdec = (const float*)d_in[1];
    const float* W1 = (const float*)d_in[2];
    const float* b1 = (const float*)d_in[3];
    const float* W2 = (const float*)d_in[4];
    const float* b2 = (const float*)d_in[5];
    float* out = (float*)d_out;
    float* ctx = out;             // [32,1024]
    float* attn = out + NB * DE;  // [32,2048,1]

    cudaFuncSetAttribute(k_energies_mma, cudaFuncAttributeMaxDynamicSharedMemorySize, SM_TOTAL);

    k_asplit<<<(NB * NS * DE) / (256 * 4), 256>>>(henc);
    k_w1split<<<dim3(32, 32), dim3(32, 8)>>>(W1);
    k_decproj<<<dim3(4, NB), 256>>>(hdec, W1, b1);
    k_energies_mma<<<dim3(16, NB), 256, SM_TOTAL>>>(W2, b2);
    k_softmax<<<NB, 256>>>(attn);
    k_ctxpart<<<dim3(16, NB), 256>>>(henc, attn);
    k_ctxred<<<128, 256>>>(ctx);
}

// round 7
// speedup vs baseline: 8.4670x; 2.3389x over previous
#include <cuda_runtime.h>
#include <cuda_fp16.h>
#include <cstdint>

#define NB 32
#define NS 2048
#define DE 1024
#define NU 1024

// ---------------- scratch (static device arrays; no runtime allocation) ----------------
__device__ float g_dp[NB * NU];                 // dec_proj + b1 (exact fp32)
__device__ float g_e2[NB * NS];                 // energies2 pre-softmax
__device__ float g_cpart[16 * NB * DE];         // context partials
__device__ __half g_w1t[NU * DE];               // W1enc^T fp16 [u][k]
__device__ __half g_ah[(size_t)NB * NS * DE];   // henc fp16 [row][k]

// ---------------- helpers ----------------
__device__ __forceinline__ uint32_t smem_u32(const void* p) {
    uint32_t a;
    asm("{ .reg .u64 t; cvta.to.shared.u64 t, %1; cvt.u32.u64 %0, t; }" : "=r"(a) : "l"(p));
    return a;
}
#define SWZ(x) ((x) ^ (((x) >> 3) & 0x70))

__device__ __forceinline__ void cpa16(uint32_t dst, const void* src) {
    asm volatile("cp.async.cg.shared.global [%0], [%1], 16;" :: "r"(dst), "l"(src));
}
__device__ __forceinline__ void ldsm4(uint32_t* r, uint32_t addr) {
    asm volatile("ldmatrix.sync.aligned.m8n8.x4.shared.b16 {%0,%1,%2,%3}, [%4];"
                 : "=r"(r[0]), "=r"(r[1]), "=r"(r[2]), "=r"(r[3]) : "r"(addr));
}
__device__ __forceinline__ void mma16816(float* c, const uint32_t* a, uint32_t b0, uint32_t b1) {
    asm volatile(
        "mma.sync.aligned.m16n8k16.row.col.f32.f16.f16.f32 "
        "{%0,%1,%2,%3}, {%4,%5,%6,%7}, {%8,%9}, {%0,%1,%2,%3};"
        : "+f"(c[0]), "+f"(c[1]), "+f"(c[2]), "+f"(c[3])
        : "r"(a[0]), "r"(a[1]), "r"(a[2]), "r"(a[3]), "r"(b0), "r"(b1));
}
__device__ __forceinline__ float tanh_fast(float x) {
    float t;
    asm("tanh.approx.f32 %0, %1;" : "=f"(t) : "f"(x));
    return t;
}

// ---------------- Kernel A: henc fp32 -> fp16 ----------------
__global__ void k_asplit(const float* __restrict__ henc) {
    size_t i = (size_t)blockIdx.x * 256 + threadIdx.x;  // one float4 per thread
    float4 v = ((const float4*)henc)[i];
    __half2 h0 = __floats2half2_rn(v.x, v.y);
    __half2 h1 = __floats2half2_rn(v.z, v.w);
    ((uint2*)g_ah)[i] = make_uint2(*(uint32_t*)&h0, *(uint32_t*)&h1);
}

// ---------------- Kernel 0: transpose W1enc into fp16 [u][k] ----------------
__global__ void k_w1split(const float* __restrict__ W1) {
    __shared__ float t[32][33];
    int k0 = blockIdx.x * 32, u0 = blockIdx.y * 32;
    int tx = threadIdx.x, ty = threadIdx.y;  // 32x8
#pragma unroll
    for (int i = 0; i < 32; i += 8)
        t[ty + i][tx] = W1[(size_t)(k0 + ty + i) * NU + u0 + tx];
    __syncthreads();
#pragma unroll
    for (int i = 0; i < 32; i += 8) {
        float v = t[tx][ty + i];
        g_w1t[(size_t)(u0 + ty + i) * DE + k0 + tx] = __float2half_rn(v);
    }
}

// ---------------- Kernel 1: dec_proj (exact fp32) ----------------
__global__ void k_decproj(const float* __restrict__ hdec, const float* __restrict__ W1,
                          const float* __restrict__ b1) {
    int b = blockIdx.y;
    int u = blockIdx.x * 256 + threadIdx.x;
    const float* hd = hdec + b * DE;
    float acc = b1[u];
#pragma unroll 8
    for (int k = 0; k < DE; k++)
        acc = fmaf(hd[k], W1[(size_t)(DE + k) * NU + u], acc);
    g_dp[b * NU + u] = acc;
}

// ---------------- Kernel 2: fp16 mma fused energies (R4-proven pipeline skeleton) ----------------
// CTA tile 128 rows x 128 u. 8 warps (2x4) of 64x32. K-stage 64, 2-stage pipeline.
// NSTG = 8 u-chunks (u0 = 0..896) x 16 k-stages = 128  <-- the R5/R6 bug was 64 here.
#define STG_BYTES 32768
#define SM_DP (2 * STG_BYTES)          // 65536
#define SM_W2 (SM_DP + 4096)
#define SM_EBUF (SM_W2 + 4096)
#define SM_TOTAL (SM_EBUF + 2048)      // 75776

#define NSTG 128

__global__ __launch_bounds__(256, 2) void k_energies_mma(const float* __restrict__ W2,
                                                         const float* __restrict__ b2) {
    extern __shared__ char smem[];
    uint32_t sbase = smem_u32(smem);
    int tid = threadIdx.x, lane = tid & 31, wid = tid >> 5;
    int mwarp = wid >> 2, nwarp = wid & 3;  // 2 x 4
    int sblk = blockIdx.x, b = blockIdx.y;
    size_t rowbase = (size_t)b * NS + (size_t)sblk * 128;

    float* dp_s = (float*)(smem + SM_DP);
    float* w2_s = (float*)(smem + SM_W2);
    float* e2buf = (float*)(smem + SM_EBUF);
    for (int i = tid; i < NU; i += 256) {
        dp_s[i] = g_dp[b * NU + i];
        w2_s[i] = W2[i];
    }
    for (int i = tid; i < 512; i += 256) e2buf[i] = 0.f;
    __syncthreads();

    // ldmatrix per-thread base offsets (within a stage buffer)
    uint32_t a_off[4], b_off[2];
#pragma unroll
    for (int mf = 0; mf < 4; mf++) {
        int r = mwarp * 64 + mf * 16 + (lane & 15);
        int kb = (lane >> 4) * 16;
        a_off[mf] = SWZ((uint32_t)(r * 128 + kb));
    }
#pragma unroll
    for (int nf2 = 0; nf2 < 2; nf2++) {
        int n = nwarp * 32 + nf2 * 16 + ((lane >> 4) & 1) * 8 + (lane & 7);
        int kb = ((lane >> 3) & 1) * 16;
        b_off[nf2] = SWZ((uint32_t)(n * 128 + kb));
    }

    // stage fst in [0,128): uc = fst>>4 in [0,8), u0 = uc*128 in [0,1024); k0 = (fst&15)*64
    auto issue = [&](int fst) {
        int k0 = (fst & 15) << 6;
        int u0 = (fst >> 4) << 7;
        uint32_t sA = sbase + (uint32_t)(fst & 1) * STG_BYTES;
        uint32_t sB = sA + 16384;
#pragma unroll
        for (int i = 0; i < 4; i++) {
            int idx = i * 256 + tid;
            int r = idx >> 3, kc = idx & 7;
            cpa16(sA + SWZ((uint32_t)(r * 128 + kc * 16)),
                  g_ah + (rowbase + r) * DE + k0 + kc * 8);
        }
#pragma unroll
        for (int i = 0; i < 4; i++) {
            int idx = i * 256 + tid;
            int r = idx >> 3, kc = idx & 7;
            cpa16(sB + SWZ((uint32_t)(r * 128 + kc * 16)),
                  g_w1t + (size_t)(u0 + r) * DE + k0 + kc * 8);
        }
        asm volatile("cp.async.commit_group;" ::: "memory");
    };

    float acc[4][4][4];
#pragma unroll
    for (int mf = 0; mf < 4; mf++)
#pragma unroll
        for (int nf = 0; nf < 4; nf++)
#pragma unroll
            for (int j = 0; j < 4; j++) acc[mf][nf][j] = 0.f;

    issue(0);
    for (int fst = 0; fst < NSTG; fst++) {
        if (fst + 1 < NSTG) {
            issue(fst + 1);
            asm volatile("cp.async.wait_group 1;" ::: "memory");
        } else {
            asm volatile("cp.async.wait_group 0;" ::: "memory");
        }
        __syncthreads();
        uint32_t abase = sbase + (uint32_t)(fst & 1) * STG_BYTES;
        uint32_t bbase = abase + 16384;
#pragma unroll
        for (int kk = 0; kk < 4; kk++) {
            uint32_t a[4][4], bq[2][4];
#pragma unroll
            for (int mf = 0; mf < 4; mf++) ldsm4(a[mf], abase + (a_off[mf] ^ (kk << 5)));
#pragma unroll
            for (int nf2 = 0; nf2 < 2; nf2++) ldsm4(bq[nf2], bbase + (b_off[nf2] ^ (kk << 5)));
#pragma unroll
            for (int mf = 0; mf < 4; mf++)
#pragma unroll
                for (int nf = 0; nf < 4; nf++) {
                    int nf2 = nf >> 1, h = (nf & 1) * 2;
                    mma16816(acc[mf][nf], a[mf], bq[nf2][h], bq[nf2][h + 1]);
                }
        }
        __syncthreads();

        // end of a u-chunk (16 stages): fused tanh + W2 epilogue
        if ((fst & 15) == 15) {
            int u0 = (fst >> 4) << 7;
            float rowsum[4][2];
#pragma unroll
            for (int mf = 0; mf < 4; mf++) {
                rowsum[mf][0] = 0.f;
                rowsum[mf][1] = 0.f;
            }
#pragma unroll
            for (int mf = 0; mf < 4; mf++)
#pragma unroll
                for (int nf = 0; nf < 4; nf++)
#pragma unroll
                    for (int j = 0; j < 4; j++) {
                        int u = u0 + nwarp * 32 + nf * 8 + (lane & 3) * 2 + (j & 1);
                        float e1 = acc[mf][nf][j] + dp_s[u];
                        rowsum[mf][j >> 1] = fmaf(tanh_fast(e1), w2_s[u], rowsum[mf][j >> 1]);
                        acc[mf][nf][j] = 0.f;
                    }
#pragma unroll
            for (int mf = 0; mf < 4; mf++)
#pragma unroll
                for (int hh = 0; hh < 2; hh++) {
                    float v = rowsum[mf][hh];
                    v += __shfl_xor_sync(0xffffffffu, v, 1);
                    v += __shfl_xor_sync(0xffffffffu, v, 2);
                    if ((lane & 3) == 0) {
                        int row = mwarp * 64 + mf * 16 + (lane >> 2) + hh * 8;
                        e2buf[nwarp * 128 + row] += v;  // distinct (nwarp,row) per writer
                    }
                }
        }
    }
    __syncthreads();
    if (tid < 128) {
        float v = e2buf[tid] + e2buf[128 + tid] + e2buf[256 + tid] + e2buf[384 + tid] + b2[0];
        g_e2[b * NS + sblk * 128 + tid] = fmaxf(v, 0.f);
    }
}

// ---------------- Kernel 3: softmax ----------------
__global__ void k_softmax(float* __restrict__ attn) {
    int b = blockIdx.x, t = threadIdx.x;
    __shared__ float red[256];
    float v[8];
    float mx = -1e30f;
#pragma unroll
    for (int q = 0; q < 8; q++) {
        v[q] = g_e2[b * NS + t + 256 * q];
        mx = fmaxf(mx, v[q]);
    }
    red[t] = mx;
    __syncthreads();
    for (int o = 128; o > 0; o >>= 1) {
        if (t < o) red[t] = fmaxf(red[t], red[t + o]);
        __syncthreads();
    }
    mx = red[0];
    __syncthreads();
    float s = 0.f;
#pragma unroll
    for (int q = 0; q < 8; q++) {
        v[q] = expf(v[q] - mx);
        s += v[q];
    }
    red[t] = s;
    __syncthreads();
    for (int o = 128; o > 0; o >>= 1) {
        if (t < o) red[t] += red[t + o];
        __syncthreads();
    }
    float inv = 1.f / red[0];
#pragma unroll
    for (int q = 0; q < 8; q++) attn[b * NS + t + 256 * q] = v[q] * inv;
}

// ---------------- Kernel 4: context partials ----------------
__global__ void k_ctxpart(const float* __restrict__ henc, const float* __restrict__ attn) {
    int sc = blockIdx.x, b = blockIdx.y, t = threadIdx.x;
    __shared__ float w[128];
    if (t < 128) w[t] = attn[b * NS + sc * 128 + t];
    __syncthreads();
    int d = t * 4;
    float4 acc = make_float4(0.f, 0.f, 0.f, 0.f);
    const float* hp = henc + ((size_t)b * NS + (size_t)sc * 128) * DE + d;
#pragma unroll 4
    for (int s = 0; s < 128; s++) {
        float ww = w[s];
        float4 h = *(const float4*)(hp + (size_t)s * DE);
        acc.x = fmaf(ww, h.x, acc.x);
        acc.y = fmaf(ww, h.y, acc.y);
        acc.z = fmaf(ww, h.z, acc.z);
        acc.w = fmaf(ww, h.w, acc.w);
    }
    *(float4*)&g_cpart[(size_t)(sc * NB + b) * DE + d] = acc;
}

// ---------------- Kernel 5: reduce ----------------
__global__ void k_ctxred(float* __restrict__ ctx) {
    int i = blockIdx.x * 256 + threadIdx.x;
    int b = i >> 10, d = i & 1023;
    float s = 0.f;
#pragma unroll
    for (int sc = 0; sc < 16; sc++) s += g_cpart[(size_t)(sc * NB + b) * DE + d];
    ctx[i] = s;
}

extern "C" void kernel_launch(void* const* d_in, const int* in_sizes, int n_in,
                              void* d_out, int out_size) {
    const float* henc = (const float*)d_in[0];
    const float* hdec = (const float*)d_in[1];
    const float* W1 = (const float*)d_in[2];
    const float* b1 = (const float*)d_in[3];
    const float* W2 = (const float*)d_in[4];
    const float* b2 = (const float*)d_in[5];
    float* out = (float*)d_out;
    float* ctx = out;             // [32,1024]
    float* attn = out + NB * DE;  // [32,2048,1]

    cudaFuncSetAttribute(k_energies_mma, cudaFuncAttributeMaxDynamicSharedMemorySize, SM_TOTAL);

    k_asplit<<<(NB * NS * DE) / (256 * 4), 256>>>(henc);
    k_w1split<<<dim3(32, 32), dim3(32, 8)>>>(W1);
    k_decproj<<<dim3(4, NB), 256>>>(hdec, W1, b1);
    k_energies_mma<<<dim3(16, NB), 256, SM_TOTAL>>>(W2, b2);
    k_softmax<<<NB, 256>>>(attn);
    k_ctxpart<<<dim3(16, NB), 256>>>(henc, attn);
    k_ctxred<<<128, 256>>>(ctx);
}

// round 8
// speedup vs baseline: 9.2188x; 1.0888x over previous
#include <cuda_runtime.h>
#include <cuda_fp16.h>
#include <cstdint>

#define NB 32
#define NS 2048
#define DE 1024
#define NU 1024

// ---------------- scratch (static device arrays; no runtime allocation) ----------------
__device__ float g_dp[NB * NU];                 // dec_proj + b1 (exact fp32)
__device__ float g_e2[NB * NS];                 // energies2 pre-softmax
__device__ float g_cpart[16 * NB * DE];         // context partials
__device__ __half g_w1t[NU * DE];               // W1enc^T fp16 [u][k]
__device__ __half g_ah[(size_t)NB * NS * DE];   // henc fp16 [row][k]

// ---------------- helpers ----------------
__device__ __forceinline__ uint32_t smem_u32(const void* p) {
    uint32_t a;
    asm("{ .reg .u64 t; cvta.to.shared.u64 t, %1; cvt.u32.u64 %0, t; }" : "=r"(a) : "l"(p));
    return a;
}
#define SWZ(x) ((x) ^ (((x) >> 3) & 0x70))

__device__ __forceinline__ void cpa16(uint32_t dst, const void* src) {
    asm volatile("cp.async.cg.shared.global [%0], [%1], 16;" :: "r"(dst), "l"(src));
}
__device__ __forceinline__ void ldsm4(uint32_t* r, uint32_t addr) {
    asm volatile("ldmatrix.sync.aligned.m8n8.x4.shared.b16 {%0,%1,%2,%3}, [%4];"
                 : "=r"(r[0]), "=r"(r[1]), "=r"(r[2]), "=r"(r[3]) : "r"(addr));
}
__device__ __forceinline__ void mma16816(float* c, const uint32_t* a, uint32_t b0, uint32_t b1) {
    asm volatile(
        "mma.sync.aligned.m16n8k16.row.col.f32.f16.f16.f32 "
        "{%0,%1,%2,%3}, {%4,%5,%6,%7}, {%8,%9}, {%0,%1,%2,%3};"
        : "+f"(c[0]), "+f"(c[1]), "+f"(c[2]), "+f"(c[3])
        : "r"(a[0]), "r"(a[1]), "r"(a[2]), "r"(a[3]), "r"(b0), "r"(b1));
}
__device__ __forceinline__ float tanh_fast(float x) {
    float t;
    asm("tanh.approx.f32 %0, %1;" : "=f"(t) : "f"(x));
    return t;
}

// ---------------- Kernel A: henc fp32 -> fp16 ----------------
__global__ void k_asplit(const float* __restrict__ henc) {
    size_t i = (size_t)blockIdx.x * 256 + threadIdx.x;  // one float4 per thread
    float4 v = ((const float4*)henc)[i];
    __half2 h0 = __floats2half2_rn(v.x, v.y);
    __half2 h1 = __floats2half2_rn(v.z, v.w);
    ((uint2*)g_ah)[i] = make_uint2(*(uint32_t*)&h0, *(uint32_t*)&h1);
}

// ---------------- Kernel 0: transpose W1enc into fp16 [u][k] ----------------
__global__ void k_w1split(const float* __restrict__ W1) {
    __shared__ float t[32][33];
    int k0 = blockIdx.x * 32, u0 = blockIdx.y * 32;
    int tx = threadIdx.x, ty = threadIdx.y;  // 32x8
#pragma unroll
    for (int i = 0; i < 32; i += 8)
        t[ty + i][tx] = W1[(size_t)(k0 + ty + i) * NU + u0 + tx];
    __syncthreads();
#pragma unroll
    for (int i = 0; i < 32; i += 8) {
        float v = t[tx][ty + i];
        g_w1t[(size_t)(u0 + ty + i) * DE + k0 + tx] = __float2half_rn(v);
    }
}

// ---------------- Kernel 1: dec_proj (exact fp32) ----------------
__global__ void k_decproj(const float* __restrict__ hdec, const float* __restrict__ W1,
                          const float* __restrict__ b1) {
    int b = blockIdx.y;
    int u = blockIdx.x * 256 + threadIdx.x;
    const float* hd = hdec + b * DE;
    float acc = b1[u];
#pragma unroll 8
    for (int k = 0; k < DE; k++)
        acc = fmaf(hd[k], W1[(size_t)(DE + k) * NU + u], acc);
    g_dp[b * NU + u] = acc;
}

// ---------------- Kernel 2: fp16 mma fused energies — 3-stage ring, 1 sync/stage ----------------
// CTA tile 128 rows x 128 u. 8 warps (2x4) of 64x32. K-stage 64.
// NSTG = 8 u-chunks x 16 k-stages = 128 (full u range!).
#define STG_BYTES 32768
#define SM_DP (3 * STG_BYTES)          // 98304
#define SM_W2 (SM_DP + 4096)
#define SM_EBUF (SM_W2 + 4096)
#define SM_TOTAL (SM_EBUF + 2048)      // 108544

#define NSTG 128

__global__ __launch_bounds__(256, 2) void k_energies_mma(const float* __restrict__ W2,
                                                         const float* __restrict__ b2) {
    extern __shared__ char smem[];
    uint32_t sbase = smem_u32(smem);
    int tid = threadIdx.x, lane = tid & 31, wid = tid >> 5;
    int mwarp = wid >> 2, nwarp = wid & 3;  // 2 x 4
    int sblk = blockIdx.x, b = blockIdx.y;
    size_t rowbase = (size_t)b * NS + (size_t)sblk * 128;

    float* dp_s = (float*)(smem + SM_DP);
    float* w2_s = (float*)(smem + SM_W2);
    float* e2buf = (float*)(smem + SM_EBUF);
    for (int i = tid; i < NU; i += 256) {
        dp_s[i] = g_dp[b * NU + i];
        w2_s[i] = W2[i];
    }
    for (int i = tid; i < 512; i += 256) e2buf[i] = 0.f;
    __syncthreads();

    // ldmatrix per-thread base offsets (within a stage buffer)
    uint32_t a_off[4], b_off[2];
#pragma unroll
    for (int mf = 0; mf < 4; mf++) {
        int r = mwarp * 64 + mf * 16 + (lane & 15);
        int kb = (lane >> 4) * 16;
        a_off[mf] = SWZ((uint32_t)(r * 128 + kb));
    }
#pragma unroll
    for (int nf2 = 0; nf2 < 2; nf2++) {
        int n = nwarp * 32 + nf2 * 16 + ((lane >> 4) & 1) * 8 + (lane & 7);
        int kb = ((lane >> 3) & 1) * 16;
        b_off[nf2] = SWZ((uint32_t)(n * 128 + kb));
    }

    // stage fst in [0,128): uc = fst>>4 in [0,8), u0 = uc*128; k0 = (fst&15)*64
    auto issue = [&](int fst) {
        int k0 = (fst & 15) << 6;
        int u0 = (fst >> 4) << 7;
        uint32_t sA = sbase + (uint32_t)(fst % 3) * STG_BYTES;
        uint32_t sB = sA + 16384;
#pragma unroll
        for (int i = 0; i < 4; i++) {
            int idx = i * 256 + tid;
            int r = idx >> 3, kc = idx & 7;
            cpa16(sA + SWZ((uint32_t)(r * 128 + kc * 16)),
                  g_ah + (rowbase + r) * DE + k0 + kc * 8);
        }
#pragma unroll
        for (int i = 0; i < 4; i++) {
            int idx = i * 256 + tid;
            int r = idx >> 3, kc = idx & 7;
            cpa16(sB + SWZ((uint32_t)(r * 128 + kc * 16)),
                  g_w1t + (size_t)(u0 + r) * DE + k0 + kc * 8);
        }
        asm volatile("cp.async.commit_group;" ::: "memory");
    };

    float acc[4][4][4];
#pragma unroll
    for (int mf = 0; mf < 4; mf++)
#pragma unroll
        for (int nf = 0; nf < 4; nf++)
#pragma unroll
            for (int j = 0; j < 4; j++) acc[mf][nf][j] = 0.f;

    issue(0);
    issue(1);
    for (int fst = 0; fst < NSTG; fst++) {
        if (fst + 1 < NSTG)
            asm volatile("cp.async.wait_group 1;" ::: "memory");
        else
            asm volatile("cp.async.wait_group 0;" ::: "memory");
        // Single barrier per stage. Safety: issue(fst+2) below writes buf (fst+2)%3 ==
        // (fst-1)%3, last READ by compute(fst-1); this barrier (executed after all warps
        // finished compute(fst-1)) orders that read before the overwrite.
        __syncthreads();

        uint32_t abase = sbase + (uint32_t)(fst % 3) * STG_BYTES;
        uint32_t bbase = abase + 16384;
#pragma unroll
        for (int kk = 0; kk < 4; kk++) {
            uint32_t a[4][4], bq[2][4];
#pragma unroll
            for (int mf = 0; mf < 4; mf++) ldsm4(a[mf], abase + (a_off[mf] ^ (kk << 5)));
#pragma unroll
            for (int nf2 = 0; nf2 < 2; nf2++) ldsm4(bq[nf2], bbase + (b_off[nf2] ^ (kk << 5)));
#pragma unroll
            for (int mf = 0; mf < 4; mf++)
#pragma unroll
                for (int nf = 0; nf < 4; nf++) {
                    int nf2 = nf >> 1, h = (nf & 1) * 2;
                    mma16816(acc[mf][nf], a[mf], bq[nf2][h], bq[nf2][h + 1]);
                }
        }
        if (fst + 2 < NSTG) issue(fst + 2);

        // end of a u-chunk (16 stages): fused tanh + W2 epilogue
        if ((fst & 15) == 15) {
            int u0 = (fst >> 4) << 7;
            float rowsum[4][2];
#pragma unroll
            for (int mf = 0; mf < 4; mf++) {
                rowsum[mf][0] = 0.f;
                rowsum[mf][1] = 0.f;
            }
#pragma unroll
            for (int mf = 0; mf < 4; mf++)
#pragma unroll
                for (int nf = 0; nf < 4; nf++)
#pragma unroll
                    for (int j = 0; j < 4; j++) {
                        int u = u0 + nwarp * 32 + nf * 8 + (lane & 3) * 2 + (j & 1);
                        float e1 = acc[mf][nf][j] + dp_s[u];
                        rowsum[mf][j >> 1] = fmaf(tanh_fast(e1), w2_s[u], rowsum[mf][j >> 1]);
                        acc[mf][nf][j] = 0.f;
                    }
#pragma unroll
            for (int mf = 0; mf < 4; mf++)
#pragma unroll
                for (int hh = 0; hh < 2; hh++) {
                    float v = rowsum[mf][hh];
                    v += __shfl_xor_sync(0xffffffffu, v, 1);
                    v += __shfl_xor_sync(0xffffffffu, v, 2);
                    if ((lane & 3) == 0) {
                        int row = mwarp * 64 + mf * 16 + (lane >> 2) + hh * 8;
                        e2buf[nwarp * 128 + row] += v;  // distinct (nwarp,row) per writer
                    }
                }
        }
    }
    __syncthreads();
    if (tid < 128) {
        float v = e2buf[tid] + e2buf[128 + tid] + e2buf[256 + tid] + e2buf[384 + tid] + b2[0];
        g_e2[b * NS + sblk * 128 + tid] = fmaxf(v, 0.f);
    }
}

// ---------------- Kernel 3: softmax ----------------
__global__ void k_softmax(float* __restrict__ attn) {
    int b = blockIdx.x, t = threadIdx.x;
    __shared__ float red[256];
    float v[8];
    float mx = -1e30f;
#pragma unroll
    for (int q = 0; q < 8; q++) {
        v[q] = g_e2[b * NS + t + 256 * q];
        mx = fmaxf(mx, v[q]);
    }
    red[t] = mx;
    __syncthreads();
    for (int o = 128; o > 0; o >>= 1) {
        if (t < o) red[t] = fmaxf(red[t], red[t + o]);
        __syncthreads();
    }
    mx = red[0];
    __syncthreads();
    float s = 0.f;
#pragma unroll
    for (int q = 0; q < 8; q++) {
        v[q] = expf(v[q] - mx);
        s += v[q];
    }
    red[t] = s;
    __syncthreads();
    for (int o = 128; o > 0; o >>= 1) {
        if (t < o) red[t] += red[t + o];
        __syncthreads();
    }
    float inv = 1.f / red[0];
#pragma unroll
    for (int q = 0; q < 8; q++) attn[b * NS + t + 256 * q] = v[q] * inv;
}

// ---------------- Kernel 4: context partials (reads fp16 henc) ----------------
__global__ void k_ctxpart(const float* __restrict__ henc, const float* __restrict__ attn) {
    int sc = blockIdx.x, b = blockIdx.y, t = threadIdx.x;
    __shared__ float w[128];
    if (t < 128) w[t] = attn[b * NS + sc * 128 + t];
    __syncthreads();
    int d = t * 4;
    float4 acc = make_float4(0.f, 0.f, 0.f, 0.f);
    const __half* hp = g_ah + ((size_t)b * NS + (size_t)sc * 128) * DE + d;
#pragma unroll 4
    for (int s = 0; s < 128; s++) {
        float ww = w[s];
        uint2 hv = *(const uint2*)(hp + (size_t)s * DE);
        float2 f0 = __half22float2(*(const __half2*)&hv.x);
        float2 f1 = __half22float2(*(const __half2*)&hv.y);
        acc.x = fmaf(ww, f0.x, acc.x);
        acc.y = fmaf(ww, f0.y, acc.y);
        acc.z = fmaf(ww, f1.x, acc.z);
        acc.w = fmaf(ww, f1.y, acc.w);
    }
    *(float4*)&g_cpart[(size_t)(sc * NB + b) * DE + d] = acc;
}

// ---------------- Kernel 5: reduce ----------------
__global__ void k_ctxred(float* __restrict__ ctx) {
    int i = blockIdx.x * 256 + threadIdx.x;
    int b = i >> 10, d = i & 1023;
    float s = 0.f;
#pragma unroll
    for (int sc = 0; sc < 16; sc++) s += g_cpart[(size_t)(sc * NB + b) * DE + d];
    ctx[i] = s;
}

extern "C" void kernel_launch(void* const* d_in, const int* in_sizes, int n_in,
                              void* d_out, int out_size) {
    const float* henc = (const float*)d_in[0];
    const float* hdec = (const float*)d_in[1];
    const float* W1 = (const float*)d_in[2];
    const float* b1 = (const float*)d_in[3];
    const float* W2 = (const float*)d_in[4];
    const float* b2 = (const float*)d_in[5];
    float* out = (float*)d_out;
    float* ctx = out;             // [32,1024]
    float* attn = out + NB * DE;  // [32,2048,1]

    cudaFuncSetAttribute(k_energies_mma, cudaFuncAttributeMaxDynamicSharedMemorySize, SM_TOTAL);

    k_asplit<<<(NB * NS * DE) / (256 * 4), 256>>>(henc);
    k_w1split<<<dim3(32, 32), dim3(32, 8)>>>(W1);
    k_decproj<<<dim3(4, NB), 256>>>(hdec, W1, b1);
    k_energies_mma<<<dim3(16, NB), 256, SM_TOTAL>>>(W2, b2);
    k_softmax<<<NB, 256>>>(attn);
    k_ctxpart<<<dim3(16, NB), 256>>>(henc, attn);
    k_ctxred<<<128, 256>>>(ctx);
}